// round 3
// baseline (speedup 1.0000x reference)
#include <cuda_runtime.h>
#include <cstdint>

// Problem constants
#define TSTEPS 500
#define BATCH  128
#define WIN    256
#define NFILT  512
#define NCLS   10
#define MROWS  (TSTEPS * BATCH)   // 64000
#define NBF    (BATCH * NFILT)    // 65536

// Scratch (device globals: no runtime allocation allowed)
__device__ float g_proj[(size_t)TSTEPS * NBF];   // [T, B, F] = 131 MB
__device__ float g_counts[NBF];                  // [B, F]
// Weights pre-split into 2 tf32 planes, pre-permuted into mma-fragment order:
// [n0blk(4)][chunk(8)] x 8192 floats, inner = [plane(2)][s(4)][nt(16)][t(32)][slot(2)]
__device__ float g_wB[4 * 8 * 8192];             // 1 MB

// ============================================================================
// helpers
// ============================================================================
__device__ __forceinline__ uint32_t smem_u32(const void* p) {
    uint32_t a;
    asm("{ .reg .u64 t; cvta.to.shared.u64 t, %1; cvt.u32.u64 %0, t; }" : "=r"(a) : "l"(p));
    return a;
}
__device__ __forceinline__ uint32_t tf32_rna(float x) {
    uint32_t u;
    asm("cvt.rna.tf32.f32 %0, %1;" : "=r"(u) : "f"(x));
    return u;
}
// 2-way tf32 split: x ~= hi + lo (each tf32-representable, stored as f32 bits)
__device__ __forceinline__ void split2(float x, uint32_t& hi, uint32_t& lo) {
    hi = tf32_rna(x);
    lo = tf32_rna(x - __uint_as_float(hi));
}
__device__ __forceinline__ void mma8(float* c, const uint32_t* a, const uint32_t* b) {
    asm volatile(
        "mma.sync.aligned.m16n8k8.row.col.f32.tf32.tf32.f32 "
        "{%0,%1,%2,%3}, {%4,%5,%6,%7}, {%8,%9}, {%0,%1,%2,%3};"
        : "+f"(c[0]), "+f"(c[1]), "+f"(c[2]), "+f"(c[3])
        : "r"(a[0]), "r"(a[1]), "r"(a[2]), "r"(a[3]), "r"(b[0]), "r"(b[1]));
}

// ============================================================================
// Kernel 0: split W[512,256] -> 2 tf32 planes in fragment-permuted layout
// ============================================================================
__global__ __launch_bounds__(256)
void fsnn_wsplit(const float* __restrict__ Wm) {
    int i = blockIdx.x * blockDim.x + threadIdx.x;
    if (i >= NFILT * WIN) return;
    int n = i >> 8, k = i & 255;
    uint32_t hi, lo;
    split2(Wm[i], hi, lo);
    int n0   = n >> 7, nn = n & 127;
    int nt   = nn >> 3;
    int ch   = k >> 5;
    int s    = (k >> 3) & 3;
    int t    = ((nn & 7) << 2) | (k & 3);
    int slot = (k >> 2) & 1;
    size_t base = (size_t)(n0 * 8 + ch) * 8192;
    g_wB[base + (size_t)((0 * 4 + s) * 16 + nt) * 64 + t * 2 + slot] = __uint_as_float(hi);
    g_wB[base + (size_t)((1 * 4 + s) * 16 + nt) * 64 + t * 2 + slot] = __uint_as_float(lo);
}

// ============================================================================
// Kernel 1: proj = X[64000,256] @ W[512,256]^T via 3xTF32 mma.sync emulation.
// CTA tile 128x128, BK=32, 8 warps (2m x 4n), warp tile 64x32.
// Double-buffered smem; B copied with cp.async from pre-permuted global;
// A split inline to fragment-permuted smem.
// A smem: [plane(2)][s(4)][mt(8)][t(32)][slot(4)] floats = 8192/buffer
// B smem: [plane(2)][s(4)][nt(16)][t(32)][slot(2)] floats = 8192/buffer
// ============================================================================
#define GEMM_SMEM (4 * 8192 * 4)   // 131072 B

__global__ __launch_bounds__(256)
void fsnn_gemm_mma(const float* __restrict__ A) {
    extern __shared__ float sm[];
    float* sA = sm;            // 2 buffers x 8192 floats
    float* sB = sm + 16384;    // 2 buffers x 8192 floats

    const int tid  = threadIdx.x;
    const int lane = tid & 31;
    const int wid  = tid >> 5;
    const int wm   = wid >> 2;        // 0..1
    const int wn   = wid & 3;         // 0..3
    const int mblk = blockIdx.x >> 2; // 0..499
    const int nblk = blockIdx.x & 3;  // 0..3
    const int m0   = mblk * 128;
    const int n0   = nblk * 128;

    float acc[4][4][4];
#pragma unroll
    for (int i = 0; i < 4; i++)
#pragma unroll
        for (int j = 0; j < 4; j++)
#pragma unroll
            for (int q = 0; q < 4; q++) acc[i][j][q] = 0.0f;

    float4 av[4];   // A prefetch regs

    // ---- lambdas (inlined) ----
    auto loadB = [&](int ch, int buf) {
        uint32_t dst = smem_u32(sB + buf * 8192);
        const float* src = g_wB + (size_t)(nblk * 8 + ch) * 8192;
#pragma unroll
        for (int i = 0; i < 8; i++) {
            int idx = tid + i * 256;  // float4 index, 2048 total
            asm volatile("cp.async.cg.shared.global [%0], [%1], 16;"
                         :: "r"(dst + idx * 16), "l"(src + (size_t)idx * 4));
        }
        asm volatile("cp.async.commit_group;");
    };
    auto loadA = [&](int ch) {
#pragma unroll
        for (int i = 0; i < 4; i++) {
            int id = tid + i * 256;        // 1024 float4 = 128 rows x 8
            int r = id >> 3, c4 = id & 7;
            av[i] = *(const float4*)(A + (size_t)(m0 + r) * WIN + ch * 32 + c4 * 4);
        }
    };
    auto stsA = [&](int buf) {
        float* dA = sA + buf * 8192;
#pragma unroll
        for (int i = 0; i < 4; i++) {
            int id = tid + i * 256;
            int r = id >> 3, c4 = id & 7;
            int mt = r >> 4, mq = r & 15;
            float v[4] = {av[i].x, av[i].y, av[i].z, av[i].w};
#pragma unroll
            for (int j = 0; j < 4; j++) {
                int kk = c4 * 4 + j;
                int s = kk >> 3, kq = kk & 7;
                int t    = ((mq & 7) << 2) | (kq & 3);
                int slot = ((kq >> 2) << 1) | (mq >> 3);
                uint32_t hi, lo;
                split2(v[j], hi, lo);
                dA[((0 * 4 + s) * 8 + mt) * 128 + t * 4 + slot] = __uint_as_float(hi);
                dA[((1 * 4 + s) * 8 + mt) * 128 + t * 4 + slot] = __uint_as_float(lo);
            }
        }
    };
    auto compute = [&](int buf) {
        const float* bA = sA + buf * 8192;
        const float* bB = sB + buf * 8192;
#pragma unroll
        for (int s = 0; s < 4; s++) {
            uint32_t af[2][4][4];
            uint32_t bf[2][4][2];
#pragma unroll
            for (int p = 0; p < 2; p++) {
#pragma unroll
                for (int mtl = 0; mtl < 4; mtl++) {
                    int mt = wm * 4 + mtl;
                    float4 v = *(const float4*)(bA + ((p * 4 + s) * 8 + mt) * 128 + lane * 4);
                    af[p][mtl][0] = __float_as_uint(v.x);
                    af[p][mtl][1] = __float_as_uint(v.y);
                    af[p][mtl][2] = __float_as_uint(v.z);
                    af[p][mtl][3] = __float_as_uint(v.w);
                }
#pragma unroll
                for (int ntl = 0; ntl < 4; ntl++) {
                    int nt = wn * 4 + ntl;
                    float2 v = *(const float2*)(bB + ((p * 4 + s) * 16 + nt) * 64 + lane * 2);
                    bf[p][ntl][0] = __float_as_uint(v.x);
                    bf[p][ntl][1] = __float_as_uint(v.y);
                }
            }
            // 3 plane-products: hi*hi, hi*lo, lo*hi
            const int pa[3] = {0, 0, 1};
            const int pb[3] = {0, 1, 0};
#pragma unroll
            for (int pp = 0; pp < 3; pp++)
#pragma unroll
                for (int mtl = 0; mtl < 4; mtl++)
#pragma unroll
                    for (int ntl = 0; ntl < 4; ntl++)
                        mma8(acc[mtl][ntl], af[pa[pp]][mtl], bf[pb[pp]][ntl]);
        }
    };

    // ---- prologue ----
    loadA(0);
    stsA(0);
    loadB(0, 0);
    asm volatile("cp.async.wait_group 0;" ::: "memory");
    __syncthreads();

    // ---- main loop over 8 K-chunks ----
    for (int c = 0; c < 8; c++) {
        if (c < 7) {
            loadB(c + 1, (c + 1) & 1);
            loadA(c + 1);
        }
        compute(c & 1);
        if (c < 7) stsA((c + 1) & 1);
        asm volatile("cp.async.wait_group 0;" ::: "memory");
        __syncthreads();
    }

    // ---- epilogue: write acc to g_proj ----
#pragma unroll
    for (int mtl = 0; mtl < 4; mtl++) {
#pragma unroll
        for (int ntl = 0; ntl < 4; ntl++) {
            int row = m0 + wm * 64 + mtl * 16 + (lane >> 2);
            int col = n0 + wn * 32 + ntl * 8 + (lane & 3) * 2;
            float* dst = g_proj + (size_t)row * NFILT + col;
            *(float2*)dst = make_float2(acc[mtl][ntl][0], acc[mtl][ntl][1]);
            *(float2*)(dst + (size_t)8 * NFILT) = make_float2(acc[mtl][ntl][2], acc[mtl][ntl][3]);
        }
    }
}

// ----------------------------------------------------------------------------
// Kernel 2: LIF scan. One thread per (b,f) trajectory; 500 sequential steps.
// ----------------------------------------------------------------------------
__global__ __launch_bounds__(256)
void fsnn_scan() {
    const int idx = blockIdx.x * blockDim.x + threadIdx.x;   // 0..65535
    const float* __restrict__ p = g_proj + idx;

    float u = 0.0f, tr = 0.0f, cnt = 0.0f;
#pragma unroll 10
    for (int t = 0; t < TSTEPS; t++) {
        float x = p[(size_t)t * NBF];
        tr = 0.95f * tr + x;
        u  = 0.9f  * u  + tr;
        if (u > 1.0f) { cnt += 1.0f; u = 0.0f; }
    }
    g_counts[idx] = cnt;
}

// ----------------------------------------------------------------------------
// Kernel 3: decoder. out[b][c] = counts[b,:] . dec_w[c,:] + dec_b[c]
// ----------------------------------------------------------------------------
__global__ __launch_bounds__(320)
void fsnn_decoder(const float* __restrict__ dec_w,
                  const float* __restrict__ dec_b,
                  float* __restrict__ out) {
    const int b    = blockIdx.x;
    const int lane = threadIdx.x & 31;
    const int c    = threadIdx.x >> 5;     // 0..9
    if (c >= NCLS) return;

    const float* crow = g_counts + b * NFILT;
    const float* wrow = dec_w + c * NFILT;
    float s = 0.0f;
#pragma unroll 4
    for (int f = lane; f < NFILT; f += 32)
        s = fmaf(crow[f], wrow[f], s);
#pragma unroll
    for (int o = 16; o; o >>= 1) s += __shfl_xor_sync(0xFFFFFFFFu, s, o);
    if (lane == 0) out[b * NCLS + c] = s + dec_b[c];
}

// ----------------------------------------------------------------------------
extern "C" void kernel_launch(void* const* d_in, const int* in_sizes, int n_in,
                              void* d_out, int out_size) {
    const float* x     = (const float*)d_in[0];   // [500,128,256]
    const float* w     = (const float*)d_in[1];   // [512,256]
    const float* dec_w = (const float*)d_in[2];   // [10,512]
    const float* dec_b = (const float*)d_in[3];   // [10]
    float* out = (float*)d_out;                   // [128,10]

    cudaFuncSetAttribute(fsnn_gemm_mma, cudaFuncAttributeMaxDynamicSharedMemorySize, GEMM_SMEM);

    fsnn_wsplit<<<(NFILT * WIN + 255) / 256, 256>>>(w);
    fsnn_gemm_mma<<<2000, 256, GEMM_SMEM>>>(x);
    fsnn_scan<<<NBF / 256, 256>>>();
    fsnn_decoder<<<BATCH, 320>>>(dec_w, dec_b, out);
}

// round 4
// speedup vs baseline: 1.3394x; 1.3394x over previous
#include <cuda_runtime.h>
#include <cstdint>

// Problem constants
#define TSTEPS 500
#define BATCH  128
#define WIN    256
#define NFILT  512
#define NCLS   10
#define MROWS  (TSTEPS * BATCH)   // 64000
#define NBF    (BATCH * NFILT)    // 65536

// Scratch (device globals: no runtime allocation allowed)
__device__ float g_proj[(size_t)TSTEPS * NBF];   // [T, B, F] = 131 MB
__device__ float g_counts[NBF];                  // [B, F]
// Weights pre-split into 2 tf32 planes, pre-permuted into mma-fragment order:
// [n0blk(4)][chunk(8)] x 8192 floats, inner = [plane(2)][s(4)][nt(16)][t(32)][slot(2)]
__device__ float g_wB[4 * 8 * 8192];             // 1 MB

// ============================================================================
// helpers
// ============================================================================
__device__ __forceinline__ uint32_t smem_u32(const void* p) {
    uint32_t a;
    asm("{ .reg .u64 t; cvta.to.shared.u64 t, %1; cvt.u32.u64 %0, t; }" : "=r"(a) : "l"(p));
    return a;
}
__device__ __forceinline__ uint32_t tf32_rna(float x) {
    uint32_t u;
    asm("cvt.rna.tf32.f32 %0, %1;" : "=r"(u) : "f"(x));
    return u;
}
__device__ __forceinline__ void split2(float x, uint32_t& hi, uint32_t& lo) {
    hi = tf32_rna(x);
    lo = tf32_rna(x - __uint_as_float(hi));
}
__device__ __forceinline__ void mma8(float* c, const uint32_t* a, const uint32_t* b) {
    asm volatile(
        "mma.sync.aligned.m16n8k8.row.col.f32.tf32.tf32.f32 "
        "{%0,%1,%2,%3}, {%4,%5,%6,%7}, {%8,%9}, {%0,%1,%2,%3};"
        : "+f"(c[0]), "+f"(c[1]), "+f"(c[2]), "+f"(c[3])
        : "r"(a[0]), "r"(a[1]), "r"(a[2]), "r"(a[3]), "r"(b[0]), "r"(b[1]));
}

// ============================================================================
// Kernel 0: split W[512,256] -> 2 tf32 planes in fragment-permuted layout
// ============================================================================
__global__ __launch_bounds__(256)
void fsnn_wsplit(const float* __restrict__ Wm) {
    int i = blockIdx.x * blockDim.x + threadIdx.x;
    if (i >= NFILT * WIN) return;
    int n = i >> 8, k = i & 255;
    uint32_t hi, lo;
    split2(Wm[i], hi, lo);
    int n0   = n >> 7, nn = n & 127;
    int nt   = nn >> 3;
    int ch   = k >> 5;
    int s    = (k >> 3) & 3;
    int t    = ((nn & 7) << 2) | (k & 3);
    int slot = (k >> 2) & 1;
    size_t base = (size_t)(n0 * 8 + ch) * 8192;
    g_wB[base + (size_t)((0 * 4 + s) * 16 + nt) * 64 + t * 2 + slot] = __uint_as_float(hi);
    g_wB[base + (size_t)((1 * 4 + s) * 16 + nt) * 64 + t * 2 + slot] = __uint_as_float(lo);
}

// ============================================================================
// Kernel 1: proj = X[64000,256] @ W[512,256]^T via 3xTF32 mma.sync emulation.
// CTA tile 128x128, BK=32, 8 warps (2m x 4n), warp tile 64x32, 2 CTAs/SM.
// A: cp.async direct to row-major padded smem (128 x 36 floats/buffer),
//    tf32-split in registers at fragment load.
// B: cp.async from pre-split, pre-permuted global (2 planes).
// ============================================================================
#define A_ROW   36                         // 32 + 4 pad floats
#define A_BUF   (128 * A_ROW)              // 4608 floats = 18 KB
#define B_BUF   8192                       // floats = 32 KB
#define GEMM_SMEM ((2 * A_BUF + 2 * B_BUF) * 4)   // 102400 B

__global__ __launch_bounds__(256, 2)
void fsnn_gemm_mma(const float* __restrict__ A) {
    extern __shared__ float sm[];
    float* sA = sm;                  // 2 x A_BUF
    float* sB = sm + 2 * A_BUF;      // 2 x B_BUF

    const int tid  = threadIdx.x;
    const int lane = tid & 31;
    const int wid  = tid >> 5;
    const int wm   = wid >> 2;        // 0..1
    const int wn   = wid & 3;         // 0..3
    const int mblk = blockIdx.x >> 2; // 0..499
    const int nblk = blockIdx.x & 3;  // 0..3
    const int m0   = mblk * 128;
    const int n0   = nblk * 128;

    const uint32_t sA_u = smem_u32(sA);
    const uint32_t sB_u = smem_u32(sB);

    float acc[4][4][4];
#pragma unroll
    for (int i = 0; i < 4; i++)
#pragma unroll
        for (int j = 0; j < 4; j++)
#pragma unroll
            for (int q = 0; q < 4; q++) acc[i][j][q] = 0.0f;

    auto issueLoads = [&](int ch, int buf) {
        // A: 128 rows x 8 float4 -> 1024 cp.async, 4 per thread
        uint32_t dstA = sA_u + buf * (A_BUF * 4);
#pragma unroll
        for (int i = 0; i < 4; i++) {
            int id = tid + i * 256;
            int r = id >> 3, c4 = id & 7;
            asm volatile("cp.async.cg.shared.global [%0], [%1], 16;"
                         :: "r"(dstA + (r * A_ROW + c4 * 4) * 4),
                            "l"(A + (size_t)(m0 + r) * WIN + ch * 32 + c4 * 4));
        }
        // B: 2048 float4, 8 per thread
        uint32_t dstB = sB_u + buf * (B_BUF * 4);
        const float* src = g_wB + (size_t)(nblk * 8 + ch) * 8192;
#pragma unroll
        for (int i = 0; i < 8; i++) {
            int idx = tid + i * 256;
            asm volatile("cp.async.cg.shared.global [%0], [%1], 16;"
                         :: "r"(dstB + idx * 16), "l"(src + (size_t)idx * 4));
        }
        asm volatile("cp.async.commit_group;");
    };

    auto compute = [&](int buf) {
        const float* bA = sA + buf * A_BUF;
        const float* bB = sB + buf * B_BUF;
#pragma unroll
        for (int s = 0; s < 4; s++) {
            // B fragments: 2 planes x 4 n-tiles x 2 regs
            uint32_t bf[2][4][2];
#pragma unroll
            for (int p = 0; p < 2; p++)
#pragma unroll
                for (int ntl = 0; ntl < 4; ntl++) {
                    int nt = wn * 4 + ntl;
                    float2 v = *(const float2*)(bB + ((p * 4 + s) * 16 + nt) * 64 + lane * 2);
                    bf[p][ntl][0] = __float_as_uint(v.x);
                    bf[p][ntl][1] = __float_as_uint(v.y);
                }
#pragma unroll
            for (int mtl = 0; mtl < 4; mtl++) {
                int r0 = (wm * 4 + mtl) * 16 + (lane >> 2);
                int c0 = s * 8 + (lane & 3);
                float a0 = bA[r0 * A_ROW + c0];
                float a1 = bA[(r0 + 8) * A_ROW + c0];
                float a2 = bA[r0 * A_ROW + c0 + 4];
                float a3 = bA[(r0 + 8) * A_ROW + c0 + 4];
                uint32_t ahi[4], alo[4];
                split2(a0, ahi[0], alo[0]);
                split2(a1, ahi[1], alo[1]);
                split2(a2, ahi[2], alo[2]);
                split2(a3, ahi[3], alo[3]);
#pragma unroll
                for (int ntl = 0; ntl < 4; ntl++) mma8(acc[mtl][ntl], ahi, bf[0][ntl]);
#pragma unroll
                for (int ntl = 0; ntl < 4; ntl++) mma8(acc[mtl][ntl], ahi, bf[1][ntl]);
#pragma unroll
                for (int ntl = 0; ntl < 4; ntl++) mma8(acc[mtl][ntl], alo, bf[0][ntl]);
            }
        }
    };

    // ---- prologue ----
    issueLoads(0, 0);
    asm volatile("cp.async.wait_group 0;" ::: "memory");
    __syncthreads();

    // ---- main loop over 8 K-chunks ----
    for (int c = 0; c < 8; c++) {
        if (c < 7) issueLoads(c + 1, (c + 1) & 1);
        compute(c & 1);
        asm volatile("cp.async.wait_group 0;" ::: "memory");
        __syncthreads();
    }

    // ---- epilogue ----
#pragma unroll
    for (int mtl = 0; mtl < 4; mtl++) {
#pragma unroll
        for (int ntl = 0; ntl < 4; ntl++) {
            int row = m0 + wm * 64 + mtl * 16 + (lane >> 2);
            int col = n0 + wn * 32 + ntl * 8 + (lane & 3) * 2;
            float* dst = g_proj + (size_t)row * NFILT + col;
            *(float2*)dst = make_float2(acc[mtl][ntl][0], acc[mtl][ntl][1]);
            *(float2*)(dst + (size_t)8 * NFILT) = make_float2(acc[mtl][ntl][2], acc[mtl][ntl][3]);
        }
    }
}

// ----------------------------------------------------------------------------
// Kernel 2: LIF scan. One thread per (b,f) trajectory; 500 sequential steps.
// ----------------------------------------------------------------------------
__global__ __launch_bounds__(256)
void fsnn_scan() {
    const int idx = blockIdx.x * blockDim.x + threadIdx.x;   // 0..65535
    const float* __restrict__ p = g_proj + idx;

    float u = 0.0f, tr = 0.0f, cnt = 0.0f;
#pragma unroll 10
    for (int t = 0; t < TSTEPS; t++) {
        float x = p[(size_t)t * NBF];
        tr = 0.95f * tr + x;
        u  = 0.9f  * u  + tr;
        if (u > 1.0f) { cnt += 1.0f; u = 0.0f; }
    }
    g_counts[idx] = cnt;
}

// ----------------------------------------------------------------------------
// Kernel 3: decoder. out[b][c] = counts[b,:] . dec_w[c,:] + dec_b[c]
// ----------------------------------------------------------------------------
__global__ __launch_bounds__(320)
void fsnn_decoder(const float* __restrict__ dec_w,
                  const float* __restrict__ dec_b,
                  float* __restrict__ out) {
    const int b    = blockIdx.x;
    const int lane = threadIdx.x & 31;
    const int c    = threadIdx.x >> 5;     // 0..9
    if (c >= NCLS) return;

    const float* crow = g_counts + b * NFILT;
    const float* wrow = dec_w + c * NFILT;
    float s = 0.0f;
#pragma unroll 4
    for (int f = lane; f < NFILT; f += 32)
        s = fmaf(crow[f], wrow[f], s);
#pragma unroll
    for (int o = 16; o; o >>= 1) s += __shfl_xor_sync(0xFFFFFFFFu, s, o);
    if (lane == 0) out[b * NCLS + c] = s + dec_b[c];
}

// ----------------------------------------------------------------------------
extern "C" void kernel_launch(void* const* d_in, const int* in_sizes, int n_in,
                              void* d_out, int out_size) {
    const float* x     = (const float*)d_in[0];   // [500,128,256]
    const float* w     = (const float*)d_in[1];   // [512,256]
    const float* dec_w = (const float*)d_in[2];   // [10,512]
    const float* dec_b = (const float*)d_in[3];   // [10]
    float* out = (float*)d_out;                   // [128,10]

    cudaFuncSetAttribute(fsnn_gemm_mma, cudaFuncAttributeMaxDynamicSharedMemorySize, GEMM_SMEM);

    fsnn_wsplit<<<(NFILT * WIN + 255) / 256, 256>>>(w);
    fsnn_gemm_mma<<<2000, 256, GEMM_SMEM>>>(x);
    fsnn_scan<<<NBF / 256, 256>>>();
    fsnn_decoder<<<BATCH, 320>>>(dec_w, dec_b, out);
}

// round 5
// speedup vs baseline: 1.9257x; 1.4378x over previous
#include <cuda_runtime.h>
#include <cuda_fp16.h>
#include <cstdint>

// Problem constants
#define TSTEPS 500
#define BATCH  128
#define WIN    256
#define NFILT  512
#define NCLS   10
#define MROWS  (TSTEPS * BATCH)   // 64000
#define NBF    (BATCH * NFILT)    // 65536

// Scratch (device globals: no runtime allocation allowed)
__device__ float g_proj[(size_t)TSTEPS * NBF];     // [T, B, F] = 131 MB
__device__ float g_counts[NBF];                    // [B, F]
// A split into 2 fp16 planes, column-permuted within each 32-col chunk
__device__ __half g_ah[(size_t)MROWS * WIN];       // 32.75 MB
__device__ __half g_al[(size_t)MROWS * WIN];       // 32.75 MB
// W split into 2 fp16 planes, fragment-permuted:
// [nblk(4)][ch(8)] x 8192 halves, inner [p(2)][s(2)][nt(16)][lane(32)][reg(2)][slot(2)]
__device__ __half g_wB[4 * 8 * 8192];              // 512 KB

// ============================================================================
// helpers
// ============================================================================
__device__ __forceinline__ uint32_t smem_u32(const void* p) {
    uint32_t a;
    asm("{ .reg .u64 t; cvta.to.shared.u64 t, %1; cvt.u32.u64 %0, t; }" : "=r"(a) : "l"(p));
    return a;
}
__device__ __forceinline__ void mma16(float* c, const uint32_t* a, const uint32_t* b) {
    asm volatile(
        "mma.sync.aligned.m16n8k16.row.col.f32.f16.f16.f32 "
        "{%0,%1,%2,%3}, {%4,%5,%6,%7}, {%8,%9}, {%0,%1,%2,%3};"
        : "+f"(c[0]), "+f"(c[1]), "+f"(c[2]), "+f"(c[3])
        : "r"(a[0]), "r"(a[1]), "r"(a[2]), "r"(a[3]), "r"(b[0]), "r"(b[1]));
}
__device__ __forceinline__ void split2h(float x, __half& h0, __half& h1) {
    h0 = __float2half_rn(x);
    h1 = __float2half_rn(x - __half2float(h0));
}

// ============================================================================
// Kernel 0a: split X -> 2 fp16 planes, column-permuted.
// Permutation per 16-col half: group g holds cols {2g, 2g+1, 2g+8, 2g+9}
// at positions g*4..g*4+3 -> fragment loads become single LDS.64.
// One thread per 4-half output group: 64000 rows x 64 groups = 4.096M threads.
// ============================================================================
__global__ __launch_bounds__(256)
void fsnn_asplit(const float* __restrict__ X) {
    int idx = blockIdx.x * 256 + threadIdx.x;
    int row = idx >> 6, grp = idx & 63;
    int blk16 = grp >> 2, g = grp & 3;
    int base = blk16 * 16 + 2 * g;
    const float* src = X + (size_t)row * WIN;
    float2 v01 = *(const float2*)(src + base);
    float2 v89 = *(const float2*)(src + base + 8);

    __half h0, l0, h1, l1, h2, l2, h3, l3;
    split2h(v01.x, h0, l0);
    split2h(v01.y, h1, l1);
    split2h(v89.x, h2, l2);
    split2h(v89.y, h3, l3);

    size_t off = (size_t)row * WIN + grp * 4;
    __half2* dh = (__half2*)(g_ah + off);
    __half2* dl = (__half2*)(g_al + off);
    dh[0] = __halves2half2(h0, h1);
    dh[1] = __halves2half2(h2, h3);
    dl[0] = __halves2half2(l0, l1);
    dl[1] = __halves2half2(l2, l3);
}

// ============================================================================
// Kernel 0b: split W[512,256] -> 2 fp16 planes in mma-fragment-permuted layout
// ============================================================================
__global__ __launch_bounds__(256)
void fsnn_wsplit(const float* __restrict__ Wm) {
    int i = blockIdx.x * blockDim.x + threadIdx.x;
    if (i >= NFILT * WIN) return;
    int n = i >> 8, k = i & 255;
    __half h, l;
    split2h(Wm[i], h, l);

    int nblk = n >> 7, nn = n & 127, nt = nn >> 3;
    int ch = k >> 5, kk = k & 31;
    int s = kk >> 4, q = kk & 15;
    int reg = q >> 3, kr = q & 7;
    int lane = (nn & 7) * 4 + (kr >> 1);
    int slot = kr & 1;

    size_t chbase = (size_t)(nblk * 8 + ch) * 8192;
    // inner [p][s][nt][lane][reg][slot]
    size_t o0 = chbase + ((((size_t)(0 * 2 + s) * 16 + nt) * 32 + lane) * 2 + reg) * 2 + slot;
    size_t o1 = chbase + ((((size_t)(1 * 2 + s) * 16 + nt) * 32 + lane) * 2 + reg) * 2 + slot;
    g_wB[o0] = h;
    g_wB[o1] = l;
}

// ============================================================================
// Kernel 1: proj = X @ W^T via 3x fp16 mma.sync m16n8k16 (Markidis split).
// CTA tile 128x128, BK=32, 8 warps (2m x 4n), warp tile 64x32, 2 CTAs/SM.
// Everything pre-split in global; inner loop = cp.async + LDS.64 + mma only.
// ============================================================================
#define A_PITCH 96                         // 64 B data + 32 B pad per row/plane
#define A_PLANE (128 * A_PITCH)            // 12288 B
#define A_BUF_B (2 * A_PLANE)              // 24576 B
#define B_BUF_B 16384                      // 8192 halves
#define GEMM_SMEM (2 * (A_BUF_B + B_BUF_B))   // 81920 B

__global__ __launch_bounds__(256, 2)
void fsnn_gemm_mma(const float* __restrict__ dummy) {
    extern __shared__ char smem[];
    char* sA = smem;                        // 2 x A_BUF_B
    char* sB = smem + 2 * A_BUF_B;          // 2 x B_BUF_B

    const int tid  = threadIdx.x;
    const int lane = tid & 31;
    const int wid  = tid >> 5;
    const int wm   = wid >> 2;        // 0..1
    const int wn   = wid & 3;         // 0..3
    const int mblk = blockIdx.x >> 2; // 0..499
    const int nblk = blockIdx.x & 3;  // 0..3
    const int m0   = mblk * 128;

    const uint32_t sA_u = smem_u32(sA);
    const uint32_t sB_u = smem_u32(sB);

    float acc[4][4][4];
#pragma unroll
    for (int i = 0; i < 4; i++)
#pragma unroll
        for (int j = 0; j < 4; j++)
#pragma unroll
            for (int q = 0; q < 4; q++) acc[i][j][q] = 0.0f;

    auto issueLoads = [&](int ch, int buf) {
        // A: 2 planes x 128 rows x 4 x16B chunks = 1024 cp.async, 4/thread
        uint32_t dstA = sA_u + buf * A_BUF_B;
#pragma unroll
        for (int i = 0; i < 4; i++) {
            int id = tid + i * 256;
            int p = id >> 9, rid = id & 511;
            int r = rid >> 2, i16 = rid & 3;
            const __half* src = (p ? g_al : g_ah) + (size_t)(m0 + r) * WIN + ch * 32 + i16 * 8;
            asm volatile("cp.async.cg.shared.global [%0], [%1], 16;"
                         :: "r"(dstA + p * A_PLANE + r * A_PITCH + i16 * 16), "l"(src));
        }
        // B: 1024 x16B chunks, 4/thread
        uint32_t dstB = sB_u + buf * B_BUF_B;
        const __half* srcB = g_wB + (size_t)(nblk * 8 + ch) * 8192;
#pragma unroll
        for (int i = 0; i < 4; i++) {
            int idx = tid + i * 256;
            asm volatile("cp.async.cg.shared.global [%0], [%1], 16;"
                         :: "r"(dstB + idx * 16), "l"(srcB + idx * 8));
        }
        asm volatile("cp.async.commit_group;");
    };

    auto compute = [&](int buf) {
        const char* bA = sA + buf * A_BUF_B;
        const char* bB = sB + buf * B_BUF_B;
        const int g = lane & 3;
        const int rl = lane >> 2;
#pragma unroll
        for (int s = 0; s < 2; s++) {
            // B fragments: [plane][ntl] -> (b0,b1) via one LDS.64 each
            uint32_t bf[2][4][2];
#pragma unroll
            for (int p = 0; p < 2; p++)
#pragma unroll
                for (int ntl = 0; ntl < 4; ntl++) {
                    int nt = wn * 4 + ntl;
                    uint2 v = *(const uint2*)(bB + ((((p * 2 + s) * 16 + nt) * 32 + lane) * 8));
                    bf[p][ntl][0] = v.x;
                    bf[p][ntl][1] = v.y;
                }
#pragma unroll
            for (int mtl = 0; mtl < 4; mtl++) {
                int r0 = (wm * 4 + mtl) * 16 + rl;
                int co = s * 32 + g * 8;       // bytes within row
                uint2 h0a = *(const uint2*)(bA + 0 * A_PLANE + r0 * A_PITCH + co);
                uint2 h0b = *(const uint2*)(bA + 0 * A_PLANE + (r0 + 8) * A_PITCH + co);
                uint2 h1a = *(const uint2*)(bA + 1 * A_PLANE + r0 * A_PITCH + co);
                uint2 h1b = *(const uint2*)(bA + 1 * A_PLANE + (r0 + 8) * A_PITCH + co);
                uint32_t a_h0[4] = {h0a.x, h0b.x, h0a.y, h0b.y};
                uint32_t a_h1[4] = {h1a.x, h1b.x, h1a.y, h1b.y};
#pragma unroll
                for (int ntl = 0; ntl < 4; ntl++) mma16(acc[mtl][ntl], a_h0, bf[0][ntl]);
#pragma unroll
                for (int ntl = 0; ntl < 4; ntl++) mma16(acc[mtl][ntl], a_h0, bf[1][ntl]);
#pragma unroll
                for (int ntl = 0; ntl < 4; ntl++) mma16(acc[mtl][ntl], a_h1, bf[0][ntl]);
            }
        }
    };

    // ---- prologue ----
    issueLoads(0, 0);
    asm volatile("cp.async.wait_group 0;" ::: "memory");
    __syncthreads();

    // ---- main loop over 8 K-chunks ----
    for (int c = 0; c < 8; c++) {
        if (c < 7) issueLoads(c + 1, (c + 1) & 1);
        compute(c & 1);
        asm volatile("cp.async.wait_group 0;" ::: "memory");
        __syncthreads();
    }

    // ---- epilogue ----
    const int n0 = nblk * 128;
#pragma unroll
    for (int mtl = 0; mtl < 4; mtl++) {
#pragma unroll
        for (int ntl = 0; ntl < 4; ntl++) {
            int row = m0 + wm * 64 + mtl * 16 + (lane >> 2);
            int col = n0 + wn * 32 + ntl * 8 + (lane & 3) * 2;
            float* dst = g_proj + (size_t)row * NFILT + col;
            *(float2*)dst = make_float2(acc[mtl][ntl][0], acc[mtl][ntl][1]);
            *(float2*)(dst + (size_t)8 * NFILT) = make_float2(acc[mtl][ntl][2], acc[mtl][ntl][3]);
        }
    }
}

// ----------------------------------------------------------------------------
// Kernel 2: LIF scan. One thread per (b,f) trajectory; 500 sequential steps.
// ----------------------------------------------------------------------------
__global__ __launch_bounds__(256)
void fsnn_scan() {
    const int idx = blockIdx.x * blockDim.x + threadIdx.x;   // 0..65535
    const float* __restrict__ p = g_proj + idx;

    float u = 0.0f, tr = 0.0f, cnt = 0.0f;
#pragma unroll 10
    for (int t = 0; t < TSTEPS; t++) {
        float x = p[(size_t)t * NBF];
        tr = 0.95f * tr + x;
        u  = 0.9f  * u  + tr;
        if (u > 1.0f) { cnt += 1.0f; u = 0.0f; }
    }
    g_counts[idx] = cnt;
}

// ----------------------------------------------------------------------------
// Kernel 3: decoder. out[b][c] = counts[b,:] . dec_w[c,:] + dec_b[c]
// ----------------------------------------------------------------------------
__global__ __launch_bounds__(320)
void fsnn_decoder(const float* __restrict__ dec_w,
                  const float* __restrict__ dec_b,
                  float* __restrict__ out) {
    const int b    = blockIdx.x;
    const int lane = threadIdx.x & 31;
    const int c    = threadIdx.x >> 5;     // 0..9
    if (c >= NCLS) return;

    const float* crow = g_counts + b * NFILT;
    const float* wrow = dec_w + c * NFILT;
    float s = 0.0f;
#pragma unroll 4
    for (int f = lane; f < NFILT; f += 32)
        s = fmaf(crow[f], wrow[f], s);
#pragma unroll
    for (int o = 16; o; o >>= 1) s += __shfl_xor_sync(0xFFFFFFFFu, s, o);
    if (lane == 0) out[b * NCLS + c] = s + dec_b[c];
}

// ----------------------------------------------------------------------------
extern "C" void kernel_launch(void* const* d_in, const int* in_sizes, int n_in,
                              void* d_out, int out_size) {
    const float* x     = (const float*)d_in[0];   // [500,128,256]
    const float* w     = (const float*)d_in[1];   // [512,256]
    const float* dec_w = (const float*)d_in[2];   // [10,512]
    const float* dec_b = (const float*)d_in[3];   // [10]
    float* out = (float*)d_out;                   // [128,10]

    cudaFuncSetAttribute(fsnn_gemm_mma, cudaFuncAttributeMaxDynamicSharedMemorySize, GEMM_SMEM);

    fsnn_asplit<<<MROWS * 64 / 256, 256>>>(x);            // 16000 blocks
    fsnn_wsplit<<<(NFILT * WIN + 255) / 256, 256>>>(w);
    fsnn_gemm_mma<<<2000, 256, GEMM_SMEM>>>(nullptr);
    fsnn_scan<<<NBF / 256, 256>>>();
    fsnn_decoder<<<BATCH, 320>>>(dec_w, dec_b, out);
}

// round 6
// speedup vs baseline: 1.9734x; 1.0248x over previous
#include <cuda_runtime.h>
#include <cuda_fp16.h>
#include <cstdint>

// Problem constants
#define TSTEPS 500
#define BATCH  128
#define WIN    256
#define NFILT  512
#define NCLS   10
#define MROWS  (TSTEPS * BATCH)   // 64000
#define NBF    (BATCH * NFILT)    // 65536

// Scratch (device globals: no runtime allocation allowed)
__device__ float g_proj[(size_t)TSTEPS * NBF];     // [T, B, F] = 131 MB
// A split into 2 fp16 planes, column-permuted within each 32-col chunk
__device__ __half g_ah[(size_t)MROWS * WIN];       // 32.75 MB
__device__ __half g_al[(size_t)MROWS * WIN];       // 32.75 MB
// W split into 2 fp16 planes, fragment-permuted:
// [nblk(4)][ch(8)] x 8192 halves, inner [p(2)][s(2)][nt(16)][lane(32)][reg(2)][slot(2)]
__device__ __half g_wB[4 * 8 * 8192];              // 512 KB

// ============================================================================
// helpers
// ============================================================================
__device__ __forceinline__ uint32_t smem_u32(const void* p) {
    uint32_t a;
    asm("{ .reg .u64 t; cvta.to.shared.u64 t, %1; cvt.u32.u64 %0, t; }" : "=r"(a) : "l"(p));
    return a;
}
__device__ __forceinline__ void mma16(float* c, const uint32_t* a, const uint32_t* b) {
    asm volatile(
        "mma.sync.aligned.m16n8k16.row.col.f32.f16.f16.f32 "
        "{%0,%1,%2,%3}, {%4,%5,%6,%7}, {%8,%9}, {%0,%1,%2,%3};"
        : "+f"(c[0]), "+f"(c[1]), "+f"(c[2]), "+f"(c[3])
        : "r"(a[0]), "r"(a[1]), "r"(a[2]), "r"(a[3]), "r"(b[0]), "r"(b[1]));
}
__device__ __forceinline__ void split2h(float x, __half& h0, __half& h1) {
    h0 = __float2half_rn(x);
    h1 = __float2half_rn(x - __half2float(h0));
}

// ============================================================================
// Kernel 0a: split X -> 2 fp16 planes, column-permuted.
// Permutation per 16-col half: group g holds cols {2g, 2g+1, 2g+8, 2g+9}
// at positions g*4..g*4+3 -> fragment loads become single LDS.64.
// ============================================================================
__global__ __launch_bounds__(256)
void fsnn_asplit(const float* __restrict__ X) {
    int idx = blockIdx.x * 256 + threadIdx.x;
    int row = idx >> 6, grp = idx & 63;
    int blk16 = grp >> 2, g = grp & 3;
    int base = blk16 * 16 + 2 * g;
    const float* src = X + (size_t)row * WIN;
    float2 v01 = *(const float2*)(src + base);
    float2 v89 = *(const float2*)(src + base + 8);

    __half h0, l0, h1, l1, h2, l2, h3, l3;
    split2h(v01.x, h0, l0);
    split2h(v01.y, h1, l1);
    split2h(v89.x, h2, l2);
    split2h(v89.y, h3, l3);

    size_t off = (size_t)row * WIN + grp * 4;
    __half2* dh = (__half2*)(g_ah + off);
    __half2* dl = (__half2*)(g_al + off);
    dh[0] = __halves2half2(h0, h1);
    dh[1] = __halves2half2(h2, h3);
    dl[0] = __halves2half2(l0, l1);
    dl[1] = __halves2half2(l2, l3);
}

// ============================================================================
// Kernel 0b: split W -> 2 fp16 planes (fragment-permuted) + init out with bias
// ============================================================================
__global__ __launch_bounds__(256)
void fsnn_wsplit(const float* __restrict__ Wm, const float* __restrict__ dec_b,
                 float* __restrict__ out) {
    if (blockIdx.x == 0) {
        for (int j = threadIdx.x; j < BATCH * NCLS; j += 256)
            out[j] = dec_b[j % NCLS];
    }
    int i = blockIdx.x * blockDim.x + threadIdx.x;
    if (i >= NFILT * WIN) return;
    int n = i >> 8, k = i & 255;
    __half h, l;
    split2h(Wm[i], h, l);

    int nblk = n >> 7, nn = n & 127, nt = nn >> 3;
    int ch = k >> 5, kk = k & 31;
    int s = kk >> 4, q = kk & 15;
    int reg = q >> 3, kr = q & 7;
    int lane = (nn & 7) * 4 + (kr >> 1);
    int slot = kr & 1;

    size_t chbase = (size_t)(nblk * 8 + ch) * 8192;
    size_t o0 = chbase + ((((size_t)(0 * 2 + s) * 16 + nt) * 32 + lane) * 2 + reg) * 2 + slot;
    size_t o1 = chbase + ((((size_t)(1 * 2 + s) * 16 + nt) * 32 + lane) * 2 + reg) * 2 + slot;
    g_wB[o0] = h;
    g_wB[o1] = l;
}

// ============================================================================
// Kernel 1: proj = X @ W^T via 3x fp16 mma.sync m16n8k16 (Markidis split).
// CTA tile 128x128, BK=32, 8 warps (2m x 4n), warp tile 64x32, 2 CTAs/SM.
// ============================================================================
#define A_PITCH 96                         // 64 B data + 32 B pad per row/plane
#define A_PLANE (128 * A_PITCH)            // 12288 B
#define A_BUF_B (2 * A_PLANE)              // 24576 B
#define B_BUF_B 16384                      // 8192 halves
#define GEMM_SMEM (2 * (A_BUF_B + B_BUF_B))   // 81920 B

__global__ __launch_bounds__(256, 2)
void fsnn_gemm_mma() {
    extern __shared__ char smem[];
    char* sA = smem;                        // 2 x A_BUF_B
    char* sB = smem + 2 * A_BUF_B;          // 2 x B_BUF_B

    const int tid  = threadIdx.x;
    const int lane = tid & 31;
    const int wid  = tid >> 5;
    const int wm   = wid >> 2;        // 0..1
    const int wn   = wid & 3;         // 0..3
    const int mblk = blockIdx.x >> 2; // 0..499
    const int nblk = blockIdx.x & 3;  // 0..3
    const int m0   = mblk * 128;

    const uint32_t sA_u = smem_u32(sA);
    const uint32_t sB_u = smem_u32(sB);

    float acc[4][4][4];
#pragma unroll
    for (int i = 0; i < 4; i++)
#pragma unroll
        for (int j = 0; j < 4; j++)
#pragma unroll
            for (int q = 0; q < 4; q++) acc[i][j][q] = 0.0f;

    auto issueLoads = [&](int ch, int buf) {
        uint32_t dstA = sA_u + buf * A_BUF_B;
#pragma unroll
        for (int i = 0; i < 4; i++) {
            int id = tid + i * 256;
            int p = id >> 9, rid = id & 511;
            int r = rid >> 2, i16 = rid & 3;
            const __half* src = (p ? g_al : g_ah) + (size_t)(m0 + r) * WIN + ch * 32 + i16 * 8;
            asm volatile("cp.async.cg.shared.global [%0], [%1], 16;"
                         :: "r"(dstA + p * A_PLANE + r * A_PITCH + i16 * 16), "l"(src));
        }
        uint32_t dstB = sB_u + buf * B_BUF_B;
        const __half* srcB = g_wB + (size_t)(nblk * 8 + ch) * 8192;
#pragma unroll
        for (int i = 0; i < 4; i++) {
            int idx = tid + i * 256;
            asm volatile("cp.async.cg.shared.global [%0], [%1], 16;"
                         :: "r"(dstB + idx * 16), "l"(srcB + idx * 8));
        }
        asm volatile("cp.async.commit_group;");
    };

    auto compute = [&](int buf) {
        const char* bA = sA + buf * A_BUF_B;
        const char* bB = sB + buf * B_BUF_B;
        const int g = lane & 3;
        const int rl = lane >> 2;
#pragma unroll
        for (int s = 0; s < 2; s++) {
            uint32_t bf[2][4][2];
#pragma unroll
            for (int p = 0; p < 2; p++)
#pragma unroll
                for (int ntl = 0; ntl < 4; ntl++) {
                    int nt = wn * 4 + ntl;
                    uint2 v = *(const uint2*)(bB + ((((p * 2 + s) * 16 + nt) * 32 + lane) * 8));
                    bf[p][ntl][0] = v.x;
                    bf[p][ntl][1] = v.y;
                }
#pragma unroll
            for (int mtl = 0; mtl < 4; mtl++) {
                int r0 = (wm * 4 + mtl) * 16 + rl;
                int co = s * 32 + g * 8;
                uint2 h0a = *(const uint2*)(bA + 0 * A_PLANE + r0 * A_PITCH + co);
                uint2 h0b = *(const uint2*)(bA + 0 * A_PLANE + (r0 + 8) * A_PITCH + co);
                uint2 h1a = *(const uint2*)(bA + 1 * A_PLANE + r0 * A_PITCH + co);
                uint2 h1b = *(const uint2*)(bA + 1 * A_PLANE + (r0 + 8) * A_PITCH + co);
                uint32_t a_h0[4] = {h0a.x, h0b.x, h0a.y, h0b.y};
                uint32_t a_h1[4] = {h1a.x, h1b.x, h1a.y, h1b.y};
#pragma unroll
                for (int ntl = 0; ntl < 4; ntl++) mma16(acc[mtl][ntl], a_h0, bf[0][ntl]);
#pragma unroll
                for (int ntl = 0; ntl < 4; ntl++) mma16(acc[mtl][ntl], a_h0, bf[1][ntl]);
#pragma unroll
                for (int ntl = 0; ntl < 4; ntl++) mma16(acc[mtl][ntl], a_h1, bf[0][ntl]);
            }
        }
    };

    issueLoads(0, 0);
    asm volatile("cp.async.wait_group 0;" ::: "memory");
    __syncthreads();

    for (int c = 0; c < 8; c++) {
        if (c < 7) issueLoads(c + 1, (c + 1) & 1);
        compute(c & 1);
        asm volatile("cp.async.wait_group 0;" ::: "memory");
        __syncthreads();
    }

    const int n0 = nblk * 128;
#pragma unroll
    for (int mtl = 0; mtl < 4; mtl++) {
#pragma unroll
        for (int ntl = 0; ntl < 4; ntl++) {
            int row = m0 + wm * 64 + mtl * 16 + (lane >> 2);
            int col = n0 + wn * 32 + ntl * 8 + (lane & 3) * 2;
            float* dst = g_proj + (size_t)row * NFILT + col;
            *(float2*)dst = make_float2(acc[mtl][ntl][0], acc[mtl][ntl][1]);
            *(float2*)(dst + (size_t)8 * NFILT) = make_float2(acc[mtl][ntl][2], acc[mtl][ntl][3]);
        }
    }
}

// ----------------------------------------------------------------------------
// Kernel 2: LIF scan with MLP-10 software pipeline + fused decoder.
// One thread per (b,f) trajectory. Warp = one b, 32 consecutive f.
// Epilogue: per class, warp-reduce cnt*dec_w[c,f], lane0 atomicAdd to out.
// ----------------------------------------------------------------------------
#define PF 10
__global__ __launch_bounds__(256)
void fsnn_scan(const float* __restrict__ dec_w, float* __restrict__ out) {
    const int idx  = blockIdx.x * 256 + threadIdx.x;   // 0..65535 = b*512 + f
    const int lane = threadIdx.x & 31;
    const int b = idx >> 9;
    const int f = idx & 511;
    const float* __restrict__ p = g_proj + idx;

    float u = 0.0f, tr = 0.0f, cnt = 0.0f;
    float buf[PF], nxt[PF];
#pragma unroll
    for (int i = 0; i < PF; i++) buf[i] = p[(size_t)i * NBF];

    for (int t0 = 0; t0 < TSTEPS; t0 += PF) {
        if (t0 + PF < TSTEPS) {
#pragma unroll
            for (int i = 0; i < PF; i++) nxt[i] = p[(size_t)(t0 + PF + i) * NBF];
        }
#pragma unroll
        for (int i = 0; i < PF; i++) {
            tr = 0.95f * tr + buf[i];
            u  = 0.9f  * u  + tr;
            if (u > 1.0f) { cnt += 1.0f; u = 0.0f; }
        }
#pragma unroll
        for (int i = 0; i < PF; i++) buf[i] = nxt[i];
    }

    // fused decoder
#pragma unroll
    for (int c = 0; c < NCLS; c++) {
        float v = cnt * dec_w[c * NFILT + f];
#pragma unroll
        for (int o = 16; o; o >>= 1) v += __shfl_xor_sync(0xFFFFFFFFu, v, o);
        if (lane == 0) atomicAdd(&out[b * NCLS + c], v);
    }
}

// ----------------------------------------------------------------------------
extern "C" void kernel_launch(void* const* d_in, const int* in_sizes, int n_in,
                              void* d_out, int out_size) {
    const float* x     = (const float*)d_in[0];   // [500,128,256]
    const float* w     = (const float*)d_in[1];   // [512,256]
    const float* dec_w = (const float*)d_in[2];   // [10,512]
    const float* dec_b = (const float*)d_in[3];   // [10]
    float* out = (float*)d_out;                   // [128,10]

    cudaFuncSetAttribute(fsnn_gemm_mma, cudaFuncAttributeMaxDynamicSharedMemorySize, GEMM_SMEM);

    fsnn_asplit<<<MROWS * 64 / 256, 256>>>(x);
    fsnn_wsplit<<<(NFILT * WIN + 255) / 256, 256>>>(w, dec_b, out);
    fsnn_gemm_mma<<<2000, 256, GEMM_SMEM>>>();
    fsnn_scan<<<NBF / 256, 256>>>(dec_w, out);
}

// round 9
// speedup vs baseline: 2.1468x; 1.0879x over previous
#include <cuda_runtime.h>
#include <cuda_fp16.h>
#include <cstdint>

// Problem constants
#define TSTEPS 500
#define BATCH  128
#define WIN    256
#define NFILT  512
#define NCLS   10
#define MROWS  (TSTEPS * BATCH)   // 64000
#define NBF    (BATCH * NFILT)    // 65536
#define PF     10                 // scan prefetch depth

// Scratch (device globals: no runtime allocation allowed).
// All 16B-aligned: cp.async.cg ...,16 requires 16B-aligned global addresses.
__device__ __align__(16) float g_proj[(size_t)(TSTEPS + PF) * NBF];     // 133.6 MB (PF-padded)
// A in full mma-fragment layout: [p(2)][rt(4000)][ks(16)][lane(32)] x 8 halves
__device__ __align__(16) __half g_af[(size_t)2 * 4000 * 16 * 32 * 8];   // 65.5 MB
// W in full mma-fragment layout: [nblk(4)][ch(8)] x 8192 halves,
// inner: [p(2)][nt(16)][lane(32)][s(2)][reg(2)][slot(2)]
__device__ __align__(16) __half g_wB[4 * 8 * 8192];                     // 512 KB

// ============================================================================
// helpers
// ============================================================================
__device__ __forceinline__ uint32_t smem_u32(const void* p) {
    uint32_t a;
    asm("{ .reg .u64 t; cvta.to.shared.u64 t, %1; cvt.u32.u64 %0, t; }" : "=r"(a) : "l"(p));
    return a;
}
__device__ __forceinline__ void mma16(float* c, const uint32_t* a, const uint32_t* b) {
    asm volatile(
        "mma.sync.aligned.m16n8k16.row.col.f32.f16.f16.f32 "
        "{%0,%1,%2,%3}, {%4,%5,%6,%7}, {%8,%9}, {%0,%1,%2,%3};"
        : "+f"(c[0]), "+f"(c[1]), "+f"(c[2]), "+f"(c[3])
        : "r"(a[0]), "r"(a[1]), "r"(a[2]), "r"(a[3]), "r"(b[0]), "r"(b[1]));
}
__device__ __forceinline__ void split2h(float x, __half& h0, __half& h1) {
    h0 = __float2half_rn(x);
    h1 = __float2half_rn(x - __half2float(h0));
}

// ============================================================================
// Kernel 0a: split X -> 2 fp16 planes directly in mma-fragment layout.
// Thread = (rt, ks, lane): produces the 16B A-fragment for both planes.
// Fragment halves order: [(lo,k0),(lo,k0+1)][(hi,k0),(hi,k0+1)]
//                        [(lo,k0+8),(lo,k0+9)][(hi,k0+8),(hi,k0+9)]
// where lo = rt*16 + (lane>>2), hi = lo+8, k0 = ks*16 + 2*(lane&3).
// ============================================================================
__global__ __launch_bounds__(256)
void fsnn_asplit(const float* __restrict__ X) {
    int idx  = blockIdx.x * 256 + threadIdx.x;   // 0 .. 2,048,000-1
    int lane = idx & 31;
    int ks   = (idx >> 5) & 15;
    int rt   = idx >> 9;
    int rl = lane >> 2, g = lane & 3;
    int rlo = rt * 16 + rl, rhi = rlo + 8;
    int k0 = ks * 16 + 2 * g;

    float2 lo_a = *(const float2*)(X + (size_t)rlo * WIN + k0);
    float2 lo_b = *(const float2*)(X + (size_t)rlo * WIN + k0 + 8);
    float2 hi_a = *(const float2*)(X + (size_t)rhi * WIN + k0);
    float2 hi_b = *(const float2*)(X + (size_t)rhi * WIN + k0 + 8);

    __half h[8], l[8];
    split2h(lo_a.x, h[0], l[0]); split2h(lo_a.y, h[1], l[1]);
    split2h(hi_a.x, h[2], l[2]); split2h(hi_a.y, h[3], l[3]);
    split2h(lo_b.x, h[4], l[4]); split2h(lo_b.y, h[5], l[5]);
    split2h(hi_b.x, h[6], l[6]); split2h(hi_b.y, h[7], l[7]);

    size_t o0 = ((((size_t)0 * 4000 + rt) * 16 + ks) * 32 + lane) * 8;
    size_t o1 = ((((size_t)1 * 4000 + rt) * 16 + ks) * 32 + lane) * 8;
    __half2* d0 = (__half2*)(g_af + o0);
    __half2* d1 = (__half2*)(g_af + o1);
#pragma unroll
    for (int j = 0; j < 4; j++) {
        d0[j] = __halves2half2(h[2 * j], h[2 * j + 1]);
        d1[j] = __halves2half2(l[2 * j], l[2 * j + 1]);
    }
}

// ============================================================================
// Kernel 0b: split W -> 2 fp16 planes (fragment layout) + init out with bias
// ============================================================================
__global__ __launch_bounds__(256)
void fsnn_wsplit(const float* __restrict__ Wm, const float* __restrict__ dec_b,
                 float* __restrict__ out) {
    if (blockIdx.x == 0) {
        for (int j = threadIdx.x; j < BATCH * NCLS; j += 256)
            out[j] = dec_b[j % NCLS];
    }
    int i = blockIdx.x * blockDim.x + threadIdx.x;
    if (i >= NFILT * WIN) return;
    int n = i >> 8, k = i & 255;
    __half h, l;
    split2h(Wm[i], h, l);

    int nblk = n >> 7, nn = n & 127, nt = nn >> 3;
    int ch = k >> 5, kk = k & 31;
    int s = kk >> 4, q = kk & 15;
    int reg = q >> 3, kr = q & 7;
    int lane = (nn & 7) * 4 + (kr >> 1);
    int slot = kr & 1;

    size_t chbase = (size_t)(nblk * 8 + ch) * 8192;
    // inner halves index: (((p*16+nt)*32+lane)*2+s)*4 + reg*2 + slot
    size_t o0 = chbase + ((((size_t)(0 * 16 + nt) * 32 + lane) * 2 + s) * 4) + reg * 2 + slot;
    size_t o1 = chbase + ((((size_t)(1 * 16 + nt) * 32 + lane) * 2 + s) * 4) + reg * 2 + slot;
    g_wB[o0] = h;
    g_wB[o1] = l;
}

// ============================================================================
// Kernel 1: proj = X @ W^T via 3x fp16 mma.sync m16n8k16 (Markidis split).
// CTA tile 128x128, BK=32, 8 warps (2m x 4n), 2 CTAs/SM.
// 3-stage cp.async pipeline (wait_group 1); all operands pre-permuted so the
// inner loop is LDS.128 (A) / LDS.64 (B) + mma only.
// ============================================================================
#define STAGE_B   32768                     // 16 KB A + 16 KB B per stage
#define GEMM_SMEM (3 * STAGE_B)             // 98304 B

__global__ __launch_bounds__(256, 2)
void fsnn_gemm_mma() {
    extern __shared__ char smem[];
    const uint32_t sm_u = smem_u32(smem);

    const int tid  = threadIdx.x;
    const int lane = tid & 31;
    const int wid  = tid >> 5;
    const int wm   = wid >> 2;        // 0..1
    const int wn   = wid & 3;         // 0..3
    const int mblk = blockIdx.x >> 2; // 0..499
    const int nblk = blockIdx.x & 3;  // 0..3

    float acc[4][4][4];
#pragma unroll
    for (int i = 0; i < 4; i++)
#pragma unroll
        for (int j = 0; j < 4; j++)
#pragma unroll
            for (int q = 0; q < 4; q++) acc[i][j][q] = 0.0f;

    auto issueLoads = [&](int ch, int buf) {
        uint32_t dst = sm_u + buf * STAGE_B;
        // A: 1024 x 16B fragments; id -> (p, mt, s, lane)
#pragma unroll
        for (int i = 0; i < 4; i++) {
            int id = tid + i * 256;
            int p = id >> 9, mt = (id >> 6) & 7, sx = (id >> 5) & 1, ln = id & 31;
            const __half* src = g_af +
                (((((size_t)p * 4000 + mblk * 8 + mt) * 16) + ch * 2 + sx) * 32 + ln) * 8;
            asm volatile("cp.async.cg.shared.global [%0], [%1], 16;"
                         :: "r"(dst + id * 16), "l"(src));
        }
        // B: 1024 x 16B, flat
        const __half* srcB = g_wB + (size_t)(nblk * 8 + ch) * 8192;
#pragma unroll
        for (int i = 0; i < 4; i++) {
            int id = tid + i * 256;
            asm volatile("cp.async.cg.shared.global [%0], [%1], 16;"
                         :: "r"(dst + 16384 + id * 16), "l"(srcB + id * 8));
        }
        asm volatile("cp.async.commit_group;");
    };

    auto compute = [&](int buf) {
        const char* bA = smem + buf * STAGE_B;
        const char* bB = bA + 16384;
#pragma unroll
        for (int s = 0; s < 2; s++) {
            uint32_t bf[2][4][2];
#pragma unroll
            for (int p = 0; p < 2; p++)
#pragma unroll
                for (int ntl = 0; ntl < 4; ntl++) {
                    int nt = wn * 4 + ntl;
                    uint2 v = *(const uint2*)(bB + (((p * 16 + nt) * 32 + lane) * 2 + s) * 8);
                    bf[p][ntl][0] = v.x;
                    bf[p][ntl][1] = v.y;
                }
#pragma unroll
            for (int mtl = 0; mtl < 4; mtl++) {
                int mt = wm * 4 + mtl;
                uint4 v0 = *(const uint4*)(bA + (((0 * 8 + mt) * 2 + s) * 32 + lane) * 16);
                uint4 v1 = *(const uint4*)(bA + (((1 * 8 + mt) * 2 + s) * 32 + lane) * 16);
                uint32_t a_h0[4] = {v0.x, v0.y, v0.z, v0.w};
                uint32_t a_h1[4] = {v1.x, v1.y, v1.z, v1.w};
#pragma unroll
                for (int ntl = 0; ntl < 4; ntl++) mma16(acc[mtl][ntl], a_h0, bf[0][ntl]);
#pragma unroll
                for (int ntl = 0; ntl < 4; ntl++) mma16(acc[mtl][ntl], a_h0, bf[1][ntl]);
#pragma unroll
                for (int ntl = 0; ntl < 4; ntl++) mma16(acc[mtl][ntl], a_h1, bf[0][ntl]);
            }
        }
    };

    // ---- 3-stage pipeline ----
    issueLoads(0, 0);
    issueLoads(1, 1);
#pragma unroll
    for (int c = 0; c < 8; c++) {
        if (c == 7) asm volatile("cp.async.wait_group 0;" ::: "memory");
        else        asm volatile("cp.async.wait_group 1;" ::: "memory");
        __syncthreads();
        if (c + 2 < 8) issueLoads(c + 2, (c + 2) % 3);
        compute(c % 3);
    }

    // ---- epilogue ----
    const int m0 = mblk * 128;
    const int n0 = nblk * 128;
#pragma unroll
    for (int mtl = 0; mtl < 4; mtl++) {
#pragma unroll
        for (int ntl = 0; ntl < 4; ntl++) {
            int row = m0 + wm * 64 + mtl * 16 + (lane >> 2);
            int col = n0 + wn * 32 + ntl * 8 + (lane & 3) * 2;
            float* dst = g_proj + (size_t)row * NFILT + col;
            *(float2*)dst = make_float2(acc[mtl][ntl][0], acc[mtl][ntl][1]);
            *(float2*)(dst + (size_t)8 * NFILT) = make_float2(acc[mtl][ntl][2], acc[mtl][ntl][3]);
        }
    }
}

// ----------------------------------------------------------------------------
// Kernel 2: LIF scan, MLP-10 pipeline (unconditional prefetch into padded
// region) + fused decoder.
// ----------------------------------------------------------------------------
__global__ __launch_bounds__(256)
void fsnn_scan(const float* __restrict__ dec_w, float* __restrict__ out) {
    const int idx  = blockIdx.x * 256 + threadIdx.x;   // 0..65535 = b*512 + f
    const int lane = threadIdx.x & 31;
    const int b = idx >> 9;
    const int f = idx & 511;
    const float* __restrict__ p = g_proj + idx;

    float u = 0.0f, tr = 0.0f, cnt = 0.0f;
    float buf[PF], nxt[PF];
#pragma unroll
    for (int i = 0; i < PF; i++) buf[i] = __ldcs(p + (size_t)i * NBF);

#pragma unroll 1
    for (int t0 = 0; t0 < TSTEPS; t0 += PF) {
        // Unconditional prefetch (reads into the PF-step pad on last iter).
#pragma unroll
        for (int i = 0; i < PF; i++) nxt[i] = __ldcs(p + (size_t)(t0 + PF + i) * NBF);
#pragma unroll
        for (int i = 0; i < PF; i++) {
            tr = 0.95f * tr + buf[i];
            u  = 0.9f  * u  + tr;
            if (u > 1.0f) { cnt += 1.0f; u = 0.0f; }
        }
#pragma unroll
        for (int i = 0; i < PF; i++) buf[i] = nxt[i];
    }

    // fused decoder
#pragma unroll
    for (int c = 0; c < NCLS; c++) {
        float v = cnt * dec_w[c * NFILT + f];
#pragma unroll
        for (int o = 16; o; o >>= 1) v += __shfl_xor_sync(0xFFFFFFFFu, v, o);
        if (lane == 0) atomicAdd(&out[b * NCLS + c], v);
    }
}

// ----------------------------------------------------------------------------
extern "C" void kernel_launch(void* const* d_in, const int* in_sizes, int n_in,
                              void* d_out, int out_size) {
    const float* x     = (const float*)d_in[0];   // [500,128,256]
    const float* w     = (const float*)d_in[1];   // [512,256]
    const float* dec_w = (const float*)d_in[2];   // [10,512]
    const float* dec_b = (const float*)d_in[3];   // [10]
    float* out = (float*)d_out;                   // [128,10]

    static bool attr_done = false;
    if (!attr_done) {
        cudaFuncSetAttribute(fsnn_gemm_mma, cudaFuncAttributeMaxDynamicSharedMemorySize, GEMM_SMEM);
        attr_done = true;
    }

    fsnn_asplit<<<2048000 / 256, 256>>>(x);       // 8000 blocks
    fsnn_wsplit<<<(NFILT * WIN + 255) / 256, 256>>>(w, dec_b, out);
    fsnn_gemm_mma<<<2000, 256, GEMM_SMEM>>>();
    fsnn_scan<<<NBF / 256, 256>>>(dec_w, out);
}